// round 4
// baseline (speedup 1.0000x reference)
#include <cuda_runtime.h>
#include <math.h>

#define THREADS 512
#define VOCAB   32000
#define BATCH   16
#define DEC_T   128
#define ATTN_L  512
#define DMODEL  768
#define NHEADS  12
#define HASHSZ  1024
#define NWARPS  (THREADS / 32)

// ---- joint online-softmax block reduce: (m = max, s = sum exp(.-m)) ----
__device__ __forceinline__ void reduceMS(float& m, float& s,
                                         volatile float* sm, volatile float* ss) {
    const int lane = threadIdx.x & 31, w = threadIdx.x >> 5;
#pragma unroll
    for (int o = 16; o; o >>= 1) {
        float om = __shfl_xor_sync(0xffffffffu, m, o);
        float os = __shfl_xor_sync(0xffffffffu, s, o);
        float nm = fmaxf(m, om);
        s = s * __expf(m - nm) + os * __expf(om - nm);
        m = nm;
    }
    __syncthreads();
    if (lane == 0) { sm[w] = m; ss[w] = s; }
    __syncthreads();
    if (w == 0) {
        float mm = (lane < NWARPS) ? sm[lane] : -INFINITY;
        float s2 = (lane < NWARPS) ? ss[lane] : 0.f;
#pragma unroll
        for (int o = 16; o; o >>= 1) {
            float om = __shfl_xor_sync(0xffffffffu, mm, o);
            float os = __shfl_xor_sync(0xffffffffu, s2, o);
            float nm = fmaxf(mm, om);
            s2 = s2 * __expf(mm - nm) + os * __expf(om - nm);
            mm = nm;
        }
        if (lane == 0) { sm[0] = mm; ss[0] = s2; }
    }
    __syncthreads();
    m = sm[0]; s = ss[0];
}

// ---- triple reduce: (m,s) online-softmax + plain sum a (p_gen dot) ----
__device__ __forceinline__ void reduceMSA(float& m, float& s, float& a,
                                          volatile float* sm, volatile float* ss,
                                          volatile float* sa) {
    const int lane = threadIdx.x & 31, w = threadIdx.x >> 5;
#pragma unroll
    for (int o = 16; o; o >>= 1) {
        float om = __shfl_xor_sync(0xffffffffu, m, o);
        float os = __shfl_xor_sync(0xffffffffu, s, o);
        float oa = __shfl_xor_sync(0xffffffffu, a, o);
        float nm = fmaxf(m, om);
        s = s * __expf(m - nm) + os * __expf(om - nm);
        m = nm;
        a += oa;
    }
    __syncthreads();
    if (lane == 0) { sm[w] = m; ss[w] = s; sa[w] = a; }
    __syncthreads();
    if (w == 0) {
        float mm = (lane < NWARPS) ? sm[lane] : -INFINITY;
        float s2 = (lane < NWARPS) ? ss[lane] : 0.f;
        float a2 = (lane < NWARPS) ? sa[lane] : 0.f;
#pragma unroll
        for (int o = 16; o; o >>= 1) {
            float om = __shfl_xor_sync(0xffffffffu, mm, o);
            float os = __shfl_xor_sync(0xffffffffu, s2, o);
            float oa = __shfl_xor_sync(0xffffffffu, a2, o);
            float nm = fmaxf(mm, om);
            s2 = s2 * __expf(mm - nm) + os * __expf(om - nm);
            mm = nm;
            a2 += oa;
        }
        if (lane == 0) { sm[0] = mm; ss[0] = s2; sa[0] = a2; }
    }
    __syncthreads();
    m = sm[0]; s = ss[0]; a = sa[0];
}

// ---------------- fused pointer-generator kernel ----------------
// One CTA per (b,t) row; 4 CTAs/SM for phase overlap.
//   non-scattered v: out[v] = fin[v] - M + log(pg) - log(S)
//   scattered id   : out[id] = log(exp(fin[id]-M) + c_id) + log(pg) - log(S)

__global__ void __launch_bounds__(THREADS, 4)
pg_fused_kernel(const float* __restrict__ dec,
                const float* __restrict__ fin,
                const float* __restrict__ attn,
                const int*   __restrict__ enc,
                const float* __restrict__ Wpg,
                const float* __restrict__ bpg,
                float*       __restrict__ out)
{
    __shared__ float sm[NWARPS], ss[NWARPS], sa[NWARPS];
    __shared__ int   hid [HASHSZ];
    __shared__ float hval[HASHSZ];

    const int tid = threadIdx.x;
    const int bt  = blockIdx.x;
    const int b   = bt >> 7;
    const int t   = bt & (DEC_T - 1);

    hid [tid]           = -1;
    hid [tid + THREADS] = -1;
    hval[tid]           = 0.f;
    hval[tid + THREADS] = 0.f;

    // ---- 1. p_gen partial dot (no reduce yet) ----
    const float* drow = dec + (size_t)bt * DMODEL;
    float acc = 0.f;
#pragma unroll
    for (int i = tid; i < DMODEL; i += THREADS) acc += drow[i] * Wpg[i];

    // ---- 2. attention mean over heads (tid == attention position) ----
    const float* abase = attn + ((size_t)b * NHEADS * DEC_T + t) * ATTN_L + tid;
    float hs = 0.f;
#pragma unroll
    for (int h = 0; h < NHEADS; h++)
        hs += __ldcs(abase + (size_t)h * DEC_T * ATTN_L);
    const float aval = hs * (1.f / NHEADS);

    // ---- 3. ONE reduce: attn (max, sum-exp) + p_gen dot ----
    float am = aval, as = 1.f;          // exp(aval - aval) = 1
    reduceMSA(am, as, acc, sm, ss, sa);
    const float pg   = 1.f / (1.f + __expf(-(acc + bpg[0])));
    const float ae   = __expf(aval - am);

    // ---- 4. hash-aggregate attention mass by vocab id ----
    {
        const int id = enc[b * ATTN_L + tid];
        int h = id & (HASHSZ - 1);
        for (;;) {
            int prev = atomicCAS(&hid[h], -1, id);
            if (prev == -1 || prev == id) { atomicAdd(&hval[h], ae); break; }
            h = (h + 1) & (HASHSZ - 1);
        }
    }

    // ---- 5. vocab-row online softmax stats (one DRAM read) ----
    const float4* frow4 = (const float4*)(fin + (size_t)bt * VOCAB);
    float m = -INFINITY, s = 0.f;
    for (int i = tid; i < VOCAB / 4; i += THREADS) {
        float4 v = frow4[i];
        float lm = fmaxf(fmaxf(v.x, v.y), fmaxf(v.z, v.w));
        if (lm > m) { s *= __expf(m - lm); m = lm; }
        s += __expf(v.x - m) + __expf(v.y - m) + __expf(v.z - m) + __expf(v.w - m);
    }
    reduceMS(m, s, sm, ss);             // m = M, s = S

    // ---- 6. bulk output: fin + c1 (re-read from L2, evict-first) ----
    const float lco = __logf(pg) - __logf(s);
    const float c1  = lco - m;
    float4* orow4 = (float4*)(out + (size_t)bt * VOCAB);
    for (int i = tid; i < VOCAB / 4; i += THREADS) {
        float4 v = __ldcs(&frow4[i]);
        v.x += c1; v.y += c1; v.z += c1; v.w += c1;
        __stcs(&orow4[i], v);
    }
    __syncthreads();                    // order bulk stores before fixups

    // ---- 7. fixup scattered ids (<=512 of them, 2 hash slots/thread) ----
    const float coef = (1.f - pg) * s / (as * pg);
#pragma unroll
    for (int k = 0; k < 2; k++) {
        const int slot = tid + k * THREADS;
        const int id   = hid[slot];
        if (id >= 0) {
            const float c = hval[slot] * coef;
            const float e = __expf(fin[(size_t)bt * VOCAB + id] - m);
            out[(size_t)bt * VOCAB + id] = __logf(e + c) + lco;
        }
    }
}

extern "C" void kernel_launch(void* const* d_in, const int* in_sizes, int n_in,
                              void* d_out, int out_size) {
    const float* dec  = (const float*)d_in[0];
    const float* fin  = (const float*)d_in[1];
    const float* attn = (const float*)d_in[2];
    const int*   enc  = (const int*)  d_in[3];
    const float* Wpg  = (const float*)d_in[4];
    const float* bpg  = (const float*)d_in[5];
    float*       out  = (float*)d_out;

    pg_fused_kernel<<<BATCH * DEC_T, THREADS>>>(dec, fin, attn, enc, Wpg, bpg, out);
}

// round 5
// speedup vs baseline: 1.1690x; 1.1690x over previous
#include <cuda_runtime.h>
#include <math.h>

#define THREADS 512
#define VOCAB   32000
#define VOCAB4  (VOCAB / 4)          // 8000 float4
#define SMEM_V4 4096                 // float4s staged in smem (64 KB)
#define REGK    8                    // float4 groups held in registers
#define BATCH   16
#define DEC_T   128
#define ATTN_L  512
#define DMODEL  768
#define NHEADS  12
#define HASHSZ  1024
#define NWARPS  (THREADS / 32)

// ---- joint online-softmax block reduce: (m = max, s = sum exp(.-m)) ----
__device__ __forceinline__ void reduceMS(float& m, float& s,
                                         volatile float* sm, volatile float* ss) {
    const int lane = threadIdx.x & 31, w = threadIdx.x >> 5;
#pragma unroll
    for (int o = 16; o; o >>= 1) {
        float om = __shfl_xor_sync(0xffffffffu, m, o);
        float os = __shfl_xor_sync(0xffffffffu, s, o);
        float nm = fmaxf(m, om);
        s = s * __expf(m - nm) + os * __expf(om - nm);
        m = nm;
    }
    __syncthreads();
    if (lane == 0) { sm[w] = m; ss[w] = s; }
    __syncthreads();
    if (w == 0) {
        float mm = (lane < NWARPS) ? sm[lane] : -INFINITY;
        float s2 = (lane < NWARPS) ? ss[lane] : 0.f;
#pragma unroll
        for (int o = 16; o; o >>= 1) {
            float om = __shfl_xor_sync(0xffffffffu, mm, o);
            float os = __shfl_xor_sync(0xffffffffu, s2, o);
            float nm = fmaxf(mm, om);
            s2 = s2 * __expf(mm - nm) + os * __expf(om - nm);
            mm = nm;
        }
        if (lane == 0) { sm[0] = mm; ss[0] = s2; }
    }
    __syncthreads();
    m = sm[0]; s = ss[0];
}

// ---- triple reduce: (m,s) online-softmax + plain sum a (p_gen dot) ----
__device__ __forceinline__ void reduceMSA(float& m, float& s, float& a,
                                          volatile float* sm, volatile float* ss,
                                          volatile float* sa) {
    const int lane = threadIdx.x & 31, w = threadIdx.x >> 5;
#pragma unroll
    for (int o = 16; o; o >>= 1) {
        float om = __shfl_xor_sync(0xffffffffu, m, o);
        float os = __shfl_xor_sync(0xffffffffu, s, o);
        float oa = __shfl_xor_sync(0xffffffffu, a, o);
        float nm = fmaxf(m, om);
        s = s * __expf(m - nm) + os * __expf(om - nm);
        m = nm;
        a += oa;
    }
    __syncthreads();
    if (lane == 0) { sm[w] = m; ss[w] = s; sa[w] = a; }
    __syncthreads();
    if (w == 0) {
        float mm = (lane < NWARPS) ? sm[lane] : -INFINITY;
        float s2 = (lane < NWARPS) ? ss[lane] : 0.f;
        float a2 = (lane < NWARPS) ? sa[lane] : 0.f;
#pragma unroll
        for (int o = 16; o; o >>= 1) {
            float om = __shfl_xor_sync(0xffffffffu, mm, o);
            float os = __shfl_xor_sync(0xffffffffu, s2, o);
            float oa = __shfl_xor_sync(0xffffffffu, a2, o);
            float nm = fmaxf(mm, om);
            s2 = s2 * __expf(mm - nm) + os * __expf(om - nm);
            mm = nm;
            a2 += oa;
        }
        if (lane == 0) { sm[0] = mm; ss[0] = s2; sa[0] = a2; }
    }
    __syncthreads();
    m = sm[0]; s = ss[0]; a = sa[0];
}

// ---------------- fused pointer-generator kernel ----------------
// One CTA per (b,t) row, 2 CTAs/SM. The vocab row is held on-SM between
// the stats pass and the write pass: 64 KB in smem + 8 float4/thread in
// registers. fin is read from DRAM exactly once; no L2 residency needed.

__global__ void __launch_bounds__(THREADS, 2)
pg_fused_kernel(const float* __restrict__ dec,
                const float* __restrict__ fin,
                const float* __restrict__ attn,
                const int*   __restrict__ enc,
                const float* __restrict__ Wpg,
                const float* __restrict__ bpg,
                float*       __restrict__ out)
{
    extern __shared__ float4 svals[];          // SMEM_V4 float4 = 64 KB
    __shared__ float sm[NWARPS], ss[NWARPS], sa[NWARPS];
    __shared__ int   hid [HASHSZ];
    __shared__ float hval[HASHSZ];

    const int tid = threadIdx.x;
    const int bt  = blockIdx.x;
    const int b   = bt >> 7;
    const int t   = bt & (DEC_T - 1);

#pragma unroll
    for (int k = 0; k < HASHSZ / THREADS; k++) {
        hid [tid + k * THREADS] = -1;
        hval[tid + k * THREADS] = 0.f;
    }

    // ---- 1. p_gen partial dot ----
    const float* drow = dec + (size_t)bt * DMODEL;
    float acc = 0.f;
#pragma unroll
    for (int i = tid; i < DMODEL; i += THREADS) acc += drow[i] * Wpg[i];

    // ---- 2. attention mean over heads (tid == attention position) ----
    const float* abase = attn + ((size_t)b * NHEADS * DEC_T + t) * ATTN_L + tid;
    float hs = 0.f;
#pragma unroll
    for (int h = 0; h < NHEADS; h++)
        hs += __ldcs(abase + (size_t)h * DEC_T * ATTN_L);
    const float aval = hs * (1.f / NHEADS);

    // ---- 3. one reduce: attn (max, sum-exp) + p_gen dot ----
    float am = aval, as = 1.f;
    reduceMSA(am, as, acc, sm, ss, sa);
    const float pg = 1.f / (1.f + __expf(-(acc + bpg[0])));
    const float ae = __expf(aval - am);

    // ---- 4. hash-aggregate attention mass by vocab id ----
    {
        const int id = enc[b * ATTN_L + tid];
        int h = id & (HASHSZ - 1);
        for (;;) {
            int prev = atomicCAS(&hid[h], -1, id);
            if (prev == -1 || prev == id) { atomicAdd(&hval[h], ae); break; }
            h = (h + 1) & (HASHSZ - 1);
        }
    }

    // ---- 5. vocab row: single DRAM read, stage to smem + regs, stats ----
    const float4* frow4 = (const float4*)(fin + (size_t)bt * VOCAB);
    float m = -INFINITY, s = 0.f;
    float4 r[REGK];

#pragma unroll
    for (int k = 0; k < SMEM_V4 / THREADS; k++) {       // 8 groups -> smem
        const int idx = tid + k * THREADS;
        float4 v = frow4[idx];
        svals[idx] = v;
        float lm = fmaxf(fmaxf(v.x, v.y), fmaxf(v.z, v.w));
        if (lm > m) { s *= __expf(m - lm); m = lm; }
        s += __expf(v.x - m) + __expf(v.y - m) + __expf(v.z - m) + __expf(v.w - m);
    }
#pragma unroll
    for (int k = 0; k < REGK; k++) {                    // 8 groups -> regs
        const int idx = SMEM_V4 + tid + k * THREADS;
        if (idx < VOCAB4) {
            float4 v = frow4[idx];
            r[k] = v;
            float lm = fmaxf(fmaxf(v.x, v.y), fmaxf(v.z, v.w));
            if (lm > m) { s *= __expf(m - lm); m = lm; }
            s += __expf(v.x - m) + __expf(v.y - m) + __expf(v.z - m) + __expf(v.w - m);
        }
    }
    reduceMS(m, s, sm, ss);                             // m = M, s = S

    // ---- 6. bulk output from on-SM copy: fin + c1, streaming stores ----
    const float lco = __logf(pg) - __logf(s);
    const float c1  = lco - m;
    float4* orow4 = (float4*)(out + (size_t)bt * VOCAB);
#pragma unroll
    for (int k = 0; k < SMEM_V4 / THREADS; k++) {
        const int idx = tid + k * THREADS;
        float4 v = svals[idx];
        v.x += c1; v.y += c1; v.z += c1; v.w += c1;
        __stcs(&orow4[idx], v);
    }
#pragma unroll
    for (int k = 0; k < REGK; k++) {
        const int idx = SMEM_V4 + tid + k * THREADS;
        if (idx < VOCAB4) {
            float4 v = r[k];
            v.x += c1; v.y += c1; v.z += c1; v.w += c1;
            __stcs(&orow4[idx], v);
        }
    }
    __syncthreads();                    // order bulk stores before fixups

    // ---- 7. fixup scattered ids (<=512, 2 hash slots/thread) ----
    const float coef = (1.f - pg) * s / (as * pg);
#pragma unroll
    for (int k = 0; k < HASHSZ / THREADS; k++) {
        const int slot = tid + k * THREADS;
        const int id   = hid[slot];
        if (id >= 0) {
            const float c = hval[slot] * coef;
            const float e = __expf(fin[(size_t)bt * VOCAB + id] - m);
            out[(size_t)bt * VOCAB + id] = __logf(e + c) + lco;
        }
    }
}

extern "C" void kernel_launch(void* const* d_in, const int* in_sizes, int n_in,
                              void* d_out, int out_size) {
    const float* dec  = (const float*)d_in[0];   // [16,128,768]
    const float* fin  = (const float*)d_in[1];   // [16,128,32000]
    const float* attn = (const float*)d_in[2];   // [16,12,128,512]
    const int*   enc  = (const int*)  d_in[3];   // [16,512]
    const float* Wpg  = (const float*)d_in[4];   // [768,1]
    const float* bpg  = (const float*)d_in[5];   // [1]
    float*       out  = (float*)d_out;           // [16,128,32000]

    const int smem_bytes = SMEM_V4 * (int)sizeof(float4);   // 65536
    cudaFuncSetAttribute(pg_fused_kernel,
                         cudaFuncAttributeMaxDynamicSharedMemorySize, smem_bytes);

    pg_fused_kernel<<<BATCH * DEC_T, THREADS, smem_bytes>>>(
        dec, fin, attn, enc, Wpg, bpg, out);
}